// round 15
// baseline (speedup 1.0000x reference)
#include <cuda_runtime.h>
#include <math.h>

#define NGENES 512
#define NBF 128                         /* fine bins */
#define HTOT (NGENES * NBF)             /* 65536 */
#define REPL 4                          /* histogram replicas */
#define MAXFRAG 2100000
#define NMLPB (NGENES / 8)              /* 64 mlp blocks */

// L2-resident scratch (no allocations allowed -> __device__ globals).
// g_hist is zero-initialized at module load and RE-ZEROED by the mlp kernel
// after reading, so every graph replay starts from a clean histogram.
__device__ int            g_hist[REPL][HTOT];
__device__ float          g_comb[HTOT];       // cconst + L0+L1+L2 combined logits
__device__ unsigned short g_fkey[MAXFRAG];    // per-fragment packed key g*128+bin

// Exact integer reproduction of jnp.searchsorted(interior_bins, x, side='left')
// for equal-width bins: idx = ceil(x*nb/20000) - 1, clamped at 0 via trunc division.
__device__ __forceinline__ int bin_idx128(int x) {
    return (x * NBF - 1) / 20000;
}

// Fused kernel (empirically best config): "hist blocks" (5-of-7) do one
// 32-lane spread RED.ADD per motif into replica (b&3); "key blocks" (2-of-7)
// precompute packed fragment keys on the idle DRAM/ALU pipes.
__global__ void hist_and_key_kernel(const int* __restrict__ mpos,
                                    const int* __restrict__ mgene, int nmot,
                                    const int* __restrict__ coords,
                                    const int* __restrict__ fgene, int nfrag) {
    int b  = blockIdx.x;
    int r7 = b % 7, q = b / 7;

    if (r7 < 2) {
        // ---- fragment key block (2048 fragments) ----
        int kb = q * 2 + r7;
        int i  = kb * 2048 + threadIdx.x * 8;
        if (i + 7 < nfrag) {
            int4 x0 = *reinterpret_cast<const int4*>(coords + i);
            int4 x1 = *reinterpret_cast<const int4*>(coords + i + 4);
            int4 g0 = *reinterpret_cast<const int4*>(fgene + i);
            int4 g1 = *reinterpret_cast<const int4*>(fgene + i + 4);
            uint4 pk;
            pk.x = (unsigned)(g0.x * NBF + bin_idx128(x0.x))
                 | ((unsigned)(g0.y * NBF + bin_idx128(x0.y)) << 16);
            pk.y = (unsigned)(g0.z * NBF + bin_idx128(x0.z))
                 | ((unsigned)(g0.w * NBF + bin_idx128(x0.w)) << 16);
            pk.z = (unsigned)(g1.x * NBF + bin_idx128(x1.x))
                 | ((unsigned)(g1.y * NBF + bin_idx128(x1.y)) << 16);
            pk.w = (unsigned)(g1.z * NBF + bin_idx128(x1.z))
                 | ((unsigned)(g1.w * NBF + bin_idx128(x1.w)) << 16);
            *reinterpret_cast<uint4*>(g_fkey + i) = pk;
        } else if (i < nfrag) {
            for (; i < nfrag; i++)
                g_fkey[i] = (unsigned short)(fgene[i] * NBF + bin_idx128(coords[i]));
        }
    } else {
        // ---- histogram block (2048 motifs, 8 per thread) ----
        int hb = q * 5 + (r7 - 2);
        int i  = hb * 2048 + threadIdx.x * 8;
        int* __restrict__ hist = g_hist[b & 3];
        if (i + 7 < nmot) {
            int4 p0 = *reinterpret_cast<const int4*>(mpos + i);
            int4 p1 = *reinterpret_cast<const int4*>(mpos + i + 4);
            int4 g0 = *reinterpret_cast<const int4*>(mgene + i);
            int4 g1 = *reinterpret_cast<const int4*>(mgene + i + 4);
            atomicAdd(&hist[g0.x * NBF + bin_idx128(p0.x)], 1);
            atomicAdd(&hist[g0.y * NBF + bin_idx128(p0.y)], 1);
            atomicAdd(&hist[g0.z * NBF + bin_idx128(p0.z)], 1);
            atomicAdd(&hist[g0.w * NBF + bin_idx128(p0.w)], 1);
            atomicAdd(&hist[g1.x * NBF + bin_idx128(p1.x)], 1);
            atomicAdd(&hist[g1.y * NBF + bin_idx128(p1.y)], 1);
            atomicAdd(&hist[g1.z * NBF + bin_idx128(p1.z)], 1);
            atomicAdd(&hist[g1.w * NBF + bin_idx128(p1.w)], 1);
        } else if (i < nmot) {
            for (; i < nmot; i++)
                atomicAdd(&hist[mgene[i] * NBF + bin_idx128(mpos[i])], 1);
        }
    }
#if __CUDA_ARCH__ >= 900
    cudaTriggerProgrammaticLaunchCompletion();
#endif
}

__device__ __forceinline__ float wmax(float v) {
#pragma unroll
    for (int s = 16; s > 0; s >>= 1) v = fmaxf(v, __shfl_xor_sync(0xffffffffu, v, s));
    return v;
}
__device__ __forceinline__ float wsum(float v) {
#pragma unroll
    for (int s = 16; s > 0; s >>= 1) v += __shfl_xor_sync(0xffffffffu, v, s);
    return v;
}

__device__ __forceinline__ float mlp_eval(float c, const float* __restrict__ w1,
                                          const float* __restrict__ b1,
                                          const float* __restrict__ w2, float b2) {
    float acc = b2;
#pragma unroll
    for (int j = 0; j < 32; j++)
        acc += fmaxf(fmaf(c, w1[j], b1[j]), 0.0f) * w2[j];
    return acc;
}

// Warp-per-gene MLP + softmax. PDL: loads weights (independent of hist
// output) BEFORE cudaGridDependencySynchronize, then reads g_hist.
__global__ void mlp_softmax_kernel(const float* __restrict__ W1,
                                   const float* __restrict__ B1,
                                   const float* __restrict__ W2,
                                   const float* __restrict__ B2, float cconst) {
    __shared__ float w1[3][32], b1[3][32], w2[3][32];
    int t = threadIdx.x;
    if (t < 96) {
        int k = t >> 5, j = t & 31;
        w1[k][j] = W1[t];
        b1[k][j] = B1[t];
        w2[k][j] = W2[t];
    }
#if __CUDA_ARCH__ >= 900
    cudaGridDependencySynchronize();   // wait for hist_and_key completion
#endif
    __syncthreads();

    int warp = t >> 5, lane = t & 31;
    int gene = blockIdx.x * 8 + warp;
    int base = gene * NBF + lane * 4;

    int4 cf = make_int4(0, 0, 0, 0);
#pragma unroll
    for (int r = 0; r < REPL; r++) {
        int4 c = *reinterpret_cast<const int4*>(&g_hist[r][base]);
        cf.x += c.x; cf.y += c.y; cf.z += c.z; cf.w += c.w;
        *reinterpret_cast<int4*>(&g_hist[r][base]) = make_int4(0, 0, 0, 0);
    }

    // ---- binset 0 (nb=32): one bin per lane ----
    float c0 = (float)(cf.x + cf.y + cf.z + cf.w) * (32.0f / 20000.0f);
    float h = mlp_eval(c0, w1[0], b1[0], w2[0], B2[0]);
    float m = wmax(h);
    float s = wsum(__expf(h - m));
    float l0 = h - m - logf(s);

    // ---- binset 1 (nb=64): two bins per lane ----
    float ca = (float)(cf.x + cf.y) * (64.0f / 20000.0f);
    float cb = (float)(cf.z + cf.w) * (64.0f / 20000.0f);
    float ha = mlp_eval(ca, w1[1], b1[1], w2[1], B2[1]);
    float hb = mlp_eval(cb, w1[1], b1[1], w2[1], B2[1]);
    float m1 = wmax(fmaxf(ha, hb));
    float s1 = wsum(__expf(ha - m1) + __expf(hb - m1));
    float lse1 = m1 + logf(s1);
    float l1a = ha - lse1, l1b = hb - lse1;

    // ---- binset 2 (nb=128): four bins per lane ----
    const float sc2 = 128.0f / 20000.0f;
    float h0 = mlp_eval((float)cf.x * sc2, w1[2], b1[2], w2[2], B2[2]);
    float h1 = mlp_eval((float)cf.y * sc2, w1[2], b1[2], w2[2], B2[2]);
    float h2 = mlp_eval((float)cf.z * sc2, w1[2], b1[2], w2[2], B2[2]);
    float h3 = mlp_eval((float)cf.w * sc2, w1[2], b1[2], w2[2], B2[2]);
    float m2 = wmax(fmaxf(fmaxf(h0, h1), fmaxf(h2, h3)));
    float s2 = wsum(__expf(h0 - m2) + __expf(h1 - m2) +
                    __expf(h2 - m2) + __expf(h3 - m2));
    float lse2 = m2 + logf(s2);

    float4 r;
    r.x = cconst + l0 + l1a + (h0 - lse2);
    r.y = cconst + l0 + l1a + (h1 - lse2);
    r.z = cconst + l0 + l1b + (h2 - lse2);
    r.w = cconst + l0 + l1b + (h3 - lse2);
    *reinterpret_cast<float4*>(&g_comb[base]) = r;
#if __CUDA_ARCH__ >= 900
    cudaTriggerProgrammaticLaunchCompletion();
#endif
}

// Final gather: 16 fragments per thread. PDL: key loads depend only on the
// hist kernel (complete before this kernel can possibly launch, since mlp's
// trigger fires after mlp's own sync on hist), so they are issued in the
// PROLOGUE, overlapping the mlp kernel; only the g_comb gathers wait on the
// dependency sync.
__global__ void frag_kernel(float* __restrict__ out, int n) {
    int i = (blockIdx.x * blockDim.x + threadIdx.x) * 16;
    uint4 ka, kb;
    bool full = (i + 15 < n);
    if (full) {
        ka = *reinterpret_cast<const uint4*>(g_fkey + i);
        kb = *reinterpret_cast<const uint4*>(g_fkey + i + 8);
    }
#if __CUDA_ARCH__ >= 900
    cudaGridDependencySynchronize();   // wait for mlp completion (g_comb)
#endif
    if (full) {
        float4 r0, r1, r2, r3;
        r0.x = g_comb[ka.x & 0xffffu];  r0.y = g_comb[ka.x >> 16];
        r0.z = g_comb[ka.y & 0xffffu];  r0.w = g_comb[ka.y >> 16];
        r1.x = g_comb[ka.z & 0xffffu];  r1.y = g_comb[ka.z >> 16];
        r1.z = g_comb[ka.w & 0xffffu];  r1.w = g_comb[ka.w >> 16];
        r2.x = g_comb[kb.x & 0xffffu];  r2.y = g_comb[kb.x >> 16];
        r2.z = g_comb[kb.y & 0xffffu];  r2.w = g_comb[kb.y >> 16];
        r3.x = g_comb[kb.z & 0xffffu];  r3.y = g_comb[kb.z >> 16];
        r3.z = g_comb[kb.w & 0xffffu];  r3.w = g_comb[kb.w >> 16];
        *reinterpret_cast<float4*>(out + i)      = r0;
        *reinterpret_cast<float4*>(out + i + 4)  = r1;
        *reinterpret_cast<float4*>(out + i + 8)  = r2;
        *reinterpret_cast<float4*>(out + i + 12) = r3;
    } else {
        for (; i < n; i++)
            out[i] = g_comb[g_fkey[i]];
    }
}

extern "C" void kernel_launch(void* const* d_in, const int* in_sizes, int n_in,
                              void* d_out, int out_size) {
    const int*   coords = (const int*)d_in[0];   // coordinates        [2M]
    const int*   fgene  = (const int*)d_in[1];   // frag_local_gene_ix [2M]
    const int*   mpos   = (const int*)d_in[2];   // motif_positions    [5M]
    const int*   mgene  = (const int*)d_in[3];   // motif_local_gene_ix[5M]
    // d_in[4..6] = bins0/1/2 (unused: equal-width bins computed in closed form)
    const float* W1 = (const float*)d_in[7];     // (3,1,32)
    const float* B1 = (const float*)d_in[8];     // (3,32)
    const float* W2 = (const float*)d_in[9];     // (3,32,1)
    const float* B2 = (const float*)d_in[10];    // (3,1)

    int nfrag = in_sizes[0];
    int nmot  = in_sizes[2];
    float* out = (float*)d_out;

    // log(32) + log(64) + log(128) - log(20000)
    const float cconst = logf(262144.0f / 20000.0f);

    int nhb = (nmot + 2047) / 2048;   // hist blocks (8 motifs/thread, 256 thr)
    int nkb = (nfrag + 2047) / 2048;  // key blocks
    int q   = (nhb + 4) / 5;
    int q2  = (nkb + 1) / 2;
    if (q2 > q) q = q2;
    int grid = 7 * q;

    // Kernel 1: plain launch
    hist_and_key_kernel<<<grid, 256>>>(mpos, mgene, nmot, coords, fgene, nfrag);

    // Kernels 2 & 3: programmatic dependent launches (overlap launch ramps
    // and frag's key prefetch with mlp execution)
    cudaLaunchAttribute attr[1];
    attr[0].id = cudaLaunchAttributeProgrammaticStreamSerialization;
    attr[0].val.programmaticStreamSerializationAllowed = 1;

    {
        cudaLaunchConfig_t cfg = {};
        cfg.gridDim  = dim3(NMLPB, 1, 1);
        cfg.blockDim = dim3(256, 1, 1);
        cfg.attrs = attr;
        cfg.numAttrs = 1;
        cudaLaunchKernelEx(&cfg, mlp_softmax_kernel, W1, B1, W2, B2, cconst);
    }
    {
        cudaLaunchConfig_t cfg = {};
        cfg.gridDim  = dim3((unsigned)((nfrag + 4095) / 4096), 1, 1);
        cfg.blockDim = dim3(256, 1, 1);
        cfg.attrs = attr;
        cfg.numAttrs = 1;
        cudaLaunchKernelEx(&cfg, frag_kernel, out, nfrag);
    }
}

// round 16
// speedup vs baseline: 1.0292x; 1.0292x over previous
#include <cuda_runtime.h>
#include <math.h>

#define NGENES 512
#define NBF 128                         /* fine bins */
#define HTOT (NGENES * NBF)             /* 65536 */
#define REPL 4                          /* histogram replicas */
#define MAXFRAG 2100000
#define NMLPB (NGENES / 8)              /* 64 mlp blocks */

// L2-resident scratch (no allocations allowed -> __device__ globals).
// g_hist is zero-initialized at module load and RE-ZEROED by the mlp kernel
// after reading, so every graph replay starts from a clean histogram.
__device__ int            g_hist[REPL][HTOT];
__device__ float          g_comb[HTOT];       // cconst + L0+L1+L2 combined logits
__device__ unsigned short g_fkey[MAXFRAG];    // per-fragment packed key g*128+bin

// Exact integer reproduction of jnp.searchsorted(interior_bins, x, side='left')
// for equal-width bins: idx = ceil(x*nb/20000) - 1, clamped at 0 via trunc division.
__device__ __forceinline__ int bin_idx128(int x) {
    return (x * NBF - 1) / 20000;
}

// Fused kernel (empirically best config): "hist blocks" (5-of-7) do one
// 32-lane spread RED.ADD per motif into replica (b&3); "key blocks" (2-of-7)
// precompute packed fragment keys on the idle DRAM/ALU pipes.
__global__ void hist_and_key_kernel(const int* __restrict__ mpos,
                                    const int* __restrict__ mgene, int nmot,
                                    const int* __restrict__ coords,
                                    const int* __restrict__ fgene, int nfrag) {
    int b  = blockIdx.x;
    int r7 = b % 7, q = b / 7;

    if (r7 < 2) {
        // ---- fragment key block (2048 fragments) ----
        int kb = q * 2 + r7;
        int i  = kb * 2048 + threadIdx.x * 8;
        if (i + 7 < nfrag) {
            int4 x0 = *reinterpret_cast<const int4*>(coords + i);
            int4 x1 = *reinterpret_cast<const int4*>(coords + i + 4);
            int4 g0 = *reinterpret_cast<const int4*>(fgene + i);
            int4 g1 = *reinterpret_cast<const int4*>(fgene + i + 4);
            uint4 pk;
            pk.x = (unsigned)(g0.x * NBF + bin_idx128(x0.x))
                 | ((unsigned)(g0.y * NBF + bin_idx128(x0.y)) << 16);
            pk.y = (unsigned)(g0.z * NBF + bin_idx128(x0.z))
                 | ((unsigned)(g0.w * NBF + bin_idx128(x0.w)) << 16);
            pk.z = (unsigned)(g1.x * NBF + bin_idx128(x1.x))
                 | ((unsigned)(g1.y * NBF + bin_idx128(x1.y)) << 16);
            pk.w = (unsigned)(g1.z * NBF + bin_idx128(x1.z))
                 | ((unsigned)(g1.w * NBF + bin_idx128(x1.w)) << 16);
            *reinterpret_cast<uint4*>(g_fkey + i) = pk;
        } else if (i < nfrag) {
            for (; i < nfrag; i++)
                g_fkey[i] = (unsigned short)(fgene[i] * NBF + bin_idx128(coords[i]));
        }
    } else {
        // ---- histogram block (2048 motifs, 8 per thread) ----
        int hb = q * 5 + (r7 - 2);
        int i  = hb * 2048 + threadIdx.x * 8;
        int* __restrict__ hist = g_hist[b & 3];
        if (i + 7 < nmot) {
            int4 p0 = *reinterpret_cast<const int4*>(mpos + i);
            int4 p1 = *reinterpret_cast<const int4*>(mpos + i + 4);
            int4 g0 = *reinterpret_cast<const int4*>(mgene + i);
            int4 g1 = *reinterpret_cast<const int4*>(mgene + i + 4);
            atomicAdd(&hist[g0.x * NBF + bin_idx128(p0.x)], 1);
            atomicAdd(&hist[g0.y * NBF + bin_idx128(p0.y)], 1);
            atomicAdd(&hist[g0.z * NBF + bin_idx128(p0.z)], 1);
            atomicAdd(&hist[g0.w * NBF + bin_idx128(p0.w)], 1);
            atomicAdd(&hist[g1.x * NBF + bin_idx128(p1.x)], 1);
            atomicAdd(&hist[g1.y * NBF + bin_idx128(p1.y)], 1);
            atomicAdd(&hist[g1.z * NBF + bin_idx128(p1.z)], 1);
            atomicAdd(&hist[g1.w * NBF + bin_idx128(p1.w)], 1);
        } else if (i < nmot) {
            for (; i < nmot; i++)
                atomicAdd(&hist[mgene[i] * NBF + bin_idx128(mpos[i])], 1);
        }
    }
#if __CUDA_ARCH__ >= 900
    cudaTriggerProgrammaticLaunchCompletion();
#endif
}

__device__ __forceinline__ float wmax(float v) {
#pragma unroll
    for (int s = 16; s > 0; s >>= 1) v = fmaxf(v, __shfl_xor_sync(0xffffffffu, v, s));
    return v;
}
__device__ __forceinline__ float wsum(float v) {
#pragma unroll
    for (int s = 16; s > 0; s >>= 1) v += __shfl_xor_sync(0xffffffffu, v, s);
    return v;
}

__device__ __forceinline__ float mlp_eval(float c, const float* __restrict__ w1,
                                          const float* __restrict__ b1,
                                          const float* __restrict__ w2, float b2) {
    float acc = b2;
#pragma unroll
    for (int j = 0; j < 32; j++)
        acc += fmaxf(fmaf(c, w1[j], b1[j]), 0.0f) * w2[j];
    return acc;
}

// Warp-per-gene MLP + softmax. PDL: loads weights (independent of hist
// output) BEFORE cudaGridDependencySynchronize, then reads g_hist.
__global__ void mlp_softmax_kernel(const float* __restrict__ W1,
                                   const float* __restrict__ B1,
                                   const float* __restrict__ W2,
                                   const float* __restrict__ B2, float cconst) {
    __shared__ float w1[3][32], b1[3][32], w2[3][32];
    int t = threadIdx.x;
    if (t < 96) {
        int k = t >> 5, j = t & 31;
        w1[k][j] = W1[t];
        b1[k][j] = B1[t];
        w2[k][j] = W2[t];
    }
#if __CUDA_ARCH__ >= 900
    cudaGridDependencySynchronize();   // wait for hist_and_key completion
#endif
    __syncthreads();

    int warp = t >> 5, lane = t & 31;
    int gene = blockIdx.x * 8 + warp;
    int base = gene * NBF + lane * 4;

    int4 cf = make_int4(0, 0, 0, 0);
#pragma unroll
    for (int r = 0; r < REPL; r++) {
        int4 c = *reinterpret_cast<const int4*>(&g_hist[r][base]);
        cf.x += c.x; cf.y += c.y; cf.z += c.z; cf.w += c.w;
        *reinterpret_cast<int4*>(&g_hist[r][base]) = make_int4(0, 0, 0, 0);
    }

    // ---- binset 0 (nb=32): one bin per lane ----
    float c0 = (float)(cf.x + cf.y + cf.z + cf.w) * (32.0f / 20000.0f);
    float h = mlp_eval(c0, w1[0], b1[0], w2[0], B2[0]);
    float m = wmax(h);
    float s = wsum(__expf(h - m));
    float l0 = h - m - logf(s);

    // ---- binset 1 (nb=64): two bins per lane ----
    float ca = (float)(cf.x + cf.y) * (64.0f / 20000.0f);
    float cb = (float)(cf.z + cf.w) * (64.0f / 20000.0f);
    float ha = mlp_eval(ca, w1[1], b1[1], w2[1], B2[1]);
    float hb = mlp_eval(cb, w1[1], b1[1], w2[1], B2[1]);
    float m1 = wmax(fmaxf(ha, hb));
    float s1 = wsum(__expf(ha - m1) + __expf(hb - m1));
    float lse1 = m1 + logf(s1);
    float l1a = ha - lse1, l1b = hb - lse1;

    // ---- binset 2 (nb=128): four bins per lane ----
    const float sc2 = 128.0f / 20000.0f;
    float h0 = mlp_eval((float)cf.x * sc2, w1[2], b1[2], w2[2], B2[2]);
    float h1 = mlp_eval((float)cf.y * sc2, w1[2], b1[2], w2[2], B2[2]);
    float h2 = mlp_eval((float)cf.z * sc2, w1[2], b1[2], w2[2], B2[2]);
    float h3 = mlp_eval((float)cf.w * sc2, w1[2], b1[2], w2[2], B2[2]);
    float m2 = wmax(fmaxf(fmaxf(h0, h1), fmaxf(h2, h3)));
    float s2 = wsum(__expf(h0 - m2) + __expf(h1 - m2) +
                    __expf(h2 - m2) + __expf(h3 - m2));
    float lse2 = m2 + logf(s2);

    float4 r;
    r.x = cconst + l0 + l1a + (h0 - lse2);
    r.y = cconst + l0 + l1a + (h1 - lse2);
    r.z = cconst + l0 + l1b + (h2 - lse2);
    r.w = cconst + l0 + l1b + (h3 - lse2);
    *reinterpret_cast<float4*>(&g_comb[base]) = r;
#if __CUDA_ARCH__ >= 900
    cudaTriggerProgrammaticLaunchCompletion();
#endif
}

// Final gather: 8 fragments per thread from packed u16 keys (pure gather).
// PDL: waits on mlp completion (which itself waited on hist, so g_fkey and
// g_comb are both complete after the sync).
__global__ void frag_kernel(float* __restrict__ out, int n) {
#if __CUDA_ARCH__ >= 900
    cudaGridDependencySynchronize();
#endif
    int i = (blockIdx.x * blockDim.x + threadIdx.x) * 8;
    if (i + 7 < n) {
        uint4 pk = *reinterpret_cast<const uint4*>(g_fkey + i);
        float4 r0, r1;
        r0.x = g_comb[pk.x & 0xffffu];
        r0.y = g_comb[pk.x >> 16];
        r0.z = g_comb[pk.y & 0xffffu];
        r0.w = g_comb[pk.y >> 16];
        r1.x = g_comb[pk.z & 0xffffu];
        r1.y = g_comb[pk.z >> 16];
        r1.z = g_comb[pk.w & 0xffffu];
        r1.w = g_comb[pk.w >> 16];
        *reinterpret_cast<float4*>(out + i) = r0;
        *reinterpret_cast<float4*>(out + i + 4) = r1;
    } else {
        for (; i < n; i++)
            out[i] = g_comb[g_fkey[i]];
    }
}

extern "C" void kernel_launch(void* const* d_in, const int* in_sizes, int n_in,
                              void* d_out, int out_size) {
    const int*   coords = (const int*)d_in[0];   // coordinates        [2M]
    const int*   fgene  = (const int*)d_in[1];   // frag_local_gene_ix [2M]
    const int*   mpos   = (const int*)d_in[2];   // motif_positions    [5M]
    const int*   mgene  = (const int*)d_in[3];   // motif_local_gene_ix[5M]
    // d_in[4..6] = bins0/1/2 (unused: equal-width bins computed in closed form)
    const float* W1 = (const float*)d_in[7];     // (3,1,32)
    const float* B1 = (const float*)d_in[8];     // (3,32)
    const float* W2 = (const float*)d_in[9];     // (3,32,1)
    const float* B2 = (const float*)d_in[10];    // (3,1)

    int nfrag = in_sizes[0];
    int nmot  = in_sizes[2];
    float* out = (float*)d_out;

    // log(32) + log(64) + log(128) - log(20000)
    const float cconst = logf(262144.0f / 20000.0f);

    int nhb = (nmot + 2047) / 2048;   // hist blocks (8 motifs/thread, 256 thr)
    int nkb = (nfrag + 2047) / 2048;  // key blocks
    int q   = (nhb + 4) / 5;
    int q2  = (nkb + 1) / 2;
    if (q2 > q) q = q2;
    int grid = 7 * q;

    // Kernel 1: plain launch
    hist_and_key_kernel<<<grid, 256>>>(mpos, mgene, nmot, coords, fgene, nfrag);

    // Kernels 2 & 3: programmatic dependent launches (overlap launch ramps)
    cudaLaunchAttribute attr[1];
    attr[0].id = cudaLaunchAttributeProgrammaticStreamSerialization;
    attr[0].val.programmaticStreamSerializationAllowed = 1;

    {
        cudaLaunchConfig_t cfg = {};
        cfg.gridDim  = dim3(NMLPB, 1, 1);
        cfg.blockDim = dim3(256, 1, 1);
        cfg.attrs = attr;
        cfg.numAttrs = 1;
        cudaLaunchKernelEx(&cfg, mlp_softmax_kernel, W1, B1, W2, B2, cconst);
    }
    {
        cudaLaunchConfig_t cfg = {};
        cfg.gridDim  = dim3((unsigned)((nfrag + 2047) / 2048), 1, 1);
        cfg.blockDim = dim3(256, 1, 1);
        cfg.attrs = attr;
        cfg.numAttrs = 1;
        cudaLaunchKernelEx(&cfg, frag_kernel, out, nfrag);
    }
}